// round 11
// baseline (speedup 1.0000x reference)
#include <cuda_runtime.h>

typedef unsigned long long ull;

#define B_   4
#define C_   64
#define H_   96
#define W_   96
#define DD   8
#define HW   (H_*W_)          // 9216
#define HWD  (H_*W_*DD)       // 73728
#define NIDX 243

#define PX   32
#define PT   8
#define CCH  8
#define NST  72      // 9 i-shifts * 8 channel chunks
#define F1COL 36     // stride/4 odd -> perfect 4-phase LDS.128
#define F2COL 44
#define F1W  (CCH*8*F1COL)     // 2304 words
#define F2W  (CCH*10*F2COL)    // 3520 words
#define SUBW (2*F1W + 2*F2W)   // 11648 words per subtile
#define SMEM_BYTES (4*SUBW*4)  // 186368 B -> 1 block/SM, 12 warps on 4 SMSPs

#define NTILE (3*H_*B_)        // 1152 tiles; 4 per block -> grid 288

__device__ float g_m1[B_*HW];
__device__ float g_m2[B_*HW];

__device__ __forceinline__ void fma2(ull &d, ull a, ull b) {
    asm("fma.rn.f32x2 %0, %1, %2, %0;" : "+l"(d) : "l"(a), "l"(b));
}
__device__ __forceinline__ ull mul2(ull a, ull b) {
    ull d; asm("mul.rn.f32x2 %0, %1, %2;" : "=l"(d) : "l"(a), "l"(b)); return d;
}
__device__ __forceinline__ ull pack2(float lo, float hi) {
    ull r; asm("mov.b64 %0, {%1, %2};" : "=l"(r) : "f"(lo), "f"(hi)); return r;
}
__device__ __forceinline__ void unpack2(ull v, float &lo, float &hi) {
    asm("mov.b64 {%0, %1}, %2;" : "=f"(lo), "=f"(hi) : "l"(v));
}
// per-subtile barrier: 96 threads, barrier id = sub+1
__device__ __forceinline__ void subbar(int sub) {
    asm volatile("bar.sync %0, %1;" :: "r"(sub + 1), "r"(96) : "memory");
}

// ---------------------------------------------------------------------------
// 4 channels of correlation (R6 champion version: float4 loads + pack2).
// 6 LDS.128 (perfect 4-phase), 36 fma.f32x2 (72 MACs) per channel.
// ---------------------------------------------------------------------------
__device__ __forceinline__ void compute4(
    const float* __restrict__ f1s, const float* __restrict__ f2s,
    int clbase, int z, int zi, int lx0, ull acc[4][9])
{
    #pragma unroll
    for (int cu = 0; cu < 4; cu++) {
        const int cl = clbase + cu;
        const float4* p1 = (const float4*)(f1s + (cl*8 + z)*F1COL + lx0);
        float4 va = p1[0], vb = p1[1];
        ull vp[4];
        vp[0] = pack2(va.x, va.y); vp[1] = pack2(va.z, va.w);
        vp[2] = pack2(vb.x, vb.y); vp[3] = pack2(vb.z, vb.w);

        const float4* p2 = (const float4*)(f2s + (cl*10 + zi)*F2COL + lx0);
        float4 t0 = p2[0], t1 = p2[1], t2 = p2[2], t3 = p2[3];
        ull e[8], o[7];
        e[0] = pack2(t0.x, t0.y); e[1] = pack2(t0.z, t0.w);
        e[2] = pack2(t1.x, t1.y); e[3] = pack2(t1.z, t1.w);
        e[4] = pack2(t2.x, t2.y); e[5] = pack2(t2.z, t2.w);
        e[6] = pack2(t3.x, t3.y); e[7] = pack2(t3.z, t3.w);
        o[0] = pack2(t0.y, t0.z); o[1] = pack2(t0.w, t1.x);
        o[2] = pack2(t1.y, t1.z); o[3] = pack2(t1.w, t2.x);
        o[4] = pack2(t2.y, t2.z); o[5] = pack2(t2.w, t3.x);
        o[6] = pack2(t3.y, t3.z);

        #pragma unroll
        for (int xp = 0; xp < 4; xp++) {
            #pragma unroll
            for (int j = 0; j < 9; j++) {
                ull tp = (j & 1) ? o[xp + ((j-1)>>1)] : e[xp + (j>>1)];
                fma2(acc[xp][j], vp[xp], tp);
            }
        }
    }
}

// ---------------------------------------------------------------------------
// Quad-tile cost + mask kernel. 384 threads = 12 warps. Warp w: subtile
// sub = w&3 (-> SMSP sub via wid%4 law), k = w>>2. Each subtile = exact R6
// pipeline (register-staged fills, double-buffered smem, own named barrier).
// All 4 SMSPs active; subtiles fully decoupled.
// ---------------------------------------------------------------------------
__global__ void __launch_bounds__(384, 1)
cost_kernel(const float* __restrict__ f1g, const float* __restrict__ f2g,
            float* __restrict__ out, float* __restrict__ omask)
{
    extern __shared__ float sm[];

    const int tid  = threadIdx.x;
    const int wid  = tid >> 5;
    const int lane = tid & 31;
    const int sub  = wid & 3;            // subtile = SMSP
    const int k    = wid >> 2;           // 0..2
    const int stid = k*32 + lane;        // thread index within subtile (0..95)

    // subtile -> (b, y, xb)
    const int t  = blockIdx.x * 4 + sub;
    const int xb = (t % 3) * PX;
    const int y  = (t / 3) % H_;
    const int b  = t / (3 * H_);

    float* f1b0 = sm + sub*SUBW;
    float* f1b1 = f1b0 + F1W;
    float* f2b0 = f1b0 + 2*F1W;
    float* f2b1 = f1b0 + 2*F1W + F2W;

    const int txg = lane & 3;
    const int z   = lane >> 2;
    const int lx0 = txg * PT;
    const int zi  = z + k;

    // ---- per-thread fill descriptors (hoisted index math)
    int  f2off[7], f2wb[7];
    bool f2ok[7];
    #pragma unroll
    for (int it = 0; it < 7; it++) {
        int idx = stid + it*96;
        int cl  = idx / 84;
        int r   = idx - cl*84;
        int col = r >> 1;
        int q   = r & 1;
        int gx  = xb - 4 + col;
        f2ok[it]  = (gx >= 0) && (gx < W_);
        f2off[it] = cl*HWD + gx*DD + q*4;
        f2wb[it]  = (cl*10 + 1 + q*4)*F2COL + col;
    }
    int  f1off[6], f1wb[6];
    bool f1ok[6];
    #pragma unroll
    for (int it = 0; it < 6; it++) {
        int idx = stid + it*96;
        f1ok[it] = idx < 512;
        int c = idx >> 6, r = idx & 63, col = r >> 1, q = r & 1;
        f1off[it] = c*HWD + col*DD + q*4;
        f1wb[it]  = (c*8 + q*4)*F1COL + col;
    }

    // zero the z-pad planes of both f2 buffers (subtile-local)
    for (int n = stid; n < 2*CCH*2*F2COL; n += 96) {
        int p   = n / (CCH*2*F2COL);
        int r   = n - p*(CCH*2*F2COL);
        int cl  = r / (2*F2COL);
        int r2  = r - cl*(2*F2COL);
        int zp  = (r2 >= F2COL) ? 9 : 0;
        int col = (r2 >= F2COL) ? (r2 - F2COL) : r2;
        (p ? f2b1 : f2b0)[(cl*10 + zp)*F2COL + col] = 0.f;
    }

    float m1x[PT];
    {
        const float* m1p = g_m1 + b*HW + y*W_ + xb + lx0;
        float4 a = *(const float4*)(m1p);
        float4 c = *(const float4*)(m1p + 4);
        m1x[0]=a.x; m1x[1]=a.y; m1x[2]=a.z; m1x[3]=a.w;
        m1x[4]=c.x; m1x[5]=c.y; m1x[6]=c.z; m1x[7]=c.w;
    }
    const bool zedge = (zi == 0) || (zi == 9);

    // ---- prologue: fill stage 0 (i=0, cc=0). yr0 = y-4: valid when y>=4.
    {
        const float* s1 = f1g + ((size_t)(b*C_))*HWD + ((size_t)y*W_ + xb)*DD;
        #pragma unroll
        for (int it = 0; it < 6; it++) {
            if (f1ok[it]) {
                float4 v = *(const float4*)(s1 + f1off[it]);
                int wb = f1wb[it];
                f1b0[wb]=v.x; f1b0[wb+F1COL]=v.y; f1b0[wb+2*F1COL]=v.z; f1b0[wb+3*F1COL]=v.w;
            }
        }
        const int  yr0   = y - 4;
        const bool vrow0 = (yr0 >= 0);
        const float* s2 = f2g + ((size_t)(b*C_))*HWD
                          + (size_t)(vrow0 ? yr0 : 0) * (W_*DD);
        #pragma unroll
        for (int it = 0; it < 7; it++) {
            float4 v = make_float4(0.f,0.f,0.f,0.f);
            if (vrow0 && f2ok[it]) v = *(const float4*)(s2 + f2off[it]);
            int wb = f2wb[it];
            f2b0[wb]=v.x; f2b0[wb+F2COL]=v.y; f2b0[wb+2*F2COL]=v.z; f2b0[wb+3*F2COL]=v.w;
        }
    }

    ull acc[4][9];

    for (int s = 0; s < NST; s++) {
        const int par = s & 1;
        subbar(sub);   // buf[par] filled; prior use of buf[par^1] done

        const float* f1s = par ? f1b1 : f1b0;
        const float* f2s = par ? f2b1 : f2b0;
        float* f1d = par ? f1b0 : f1b1;
        float* f2d = par ? f2b0 : f2b1;

        const int i  = s >> 3;
        const int cc = s & 7;

        const int  sn    = s + 1;
        const bool hasn  = sn < NST;
        const int  in_   = sn >> 3;
        const int  ccn   = sn & 7;
        const int  yrn   = y + in_ - 4;
        const bool vrown = hasn && (yrn >= 0) && (yrn < H_);

        // ---- phase 1: LDG f2-next into registers
        float4 Bv[7];
        {
            const float* s2 = f2g + ((size_t)(b*C_ + ccn*CCH))*HWD
                              + (size_t)(vrown ? yrn : 0) * (W_*DD);
            #pragma unroll
            for (int it = 0; it < 7; it++) {
                float4 v = make_float4(0.f,0.f,0.f,0.f);
                if (vrown && f2ok[it]) v = *(const float4*)(s2 + f2off[it]);
                Bv[it] = v;
            }
        }

        if (cc == 0) {
            #pragma unroll
            for (int xp = 0; xp < 4; xp++)
                #pragma unroll
                for (int j = 0; j < 9; j++) acc[xp][j] = 0ull;
        }

        // ---- phase 2: compute channels 0-3 (covers f2 LDG latency)
        compute4(f1s, f2s, 0, z, zi, lx0, acc);

        // ---- phase 3: STS f2-next
        if (hasn) {
            #pragma unroll
            for (int it = 0; it < 7; it++) {
                int wb = f2wb[it];
                f2d[wb]=Bv[it].x; f2d[wb+F2COL]=Bv[it].y;
                f2d[wb+2*F2COL]=Bv[it].z; f2d[wb+3*F2COL]=Bv[it].w;
            }
        }

        // ---- phase 4: LDG f1-next into registers
        float4 Av[6];
        {
            const float* s1 = f1g + ((size_t)(b*C_ + ccn*CCH))*HWD
                              + ((size_t)y*W_ + xb)*DD;
            #pragma unroll
            for (int it = 0; it < 6; it++) {
                float4 v = make_float4(0.f,0.f,0.f,0.f);
                if (hasn && f1ok[it]) v = *(const float4*)(s1 + f1off[it]);
                Av[it] = v;
            }
        }

        // ---- phase 5: compute channels 4-7 (covers f1 LDG latency)
        compute4(f1s, f2s, 4, z, zi, lx0, acc);

        // ---- phase 6: STS f1-next
        if (hasn) {
            #pragma unroll
            for (int it = 0; it < 6; it++) {
                if (f1ok[it]) {
                    int wb = f1wb[it];
                    f1d[wb]=Av[it].x; f1d[wb+F1COL]=Av[it].y;
                    f1d[wb+2*F1COL]=Av[it].z; f1d[wb+3*F1COL]=Av[it].w;
                }
            }
        }

        // ---- outputs at end of each i-group
        if (cc == 7) {
            const ull scc = pack2(1.0f/64.0f, 1.0f/64.0f);
            long obase = ((long)(b*NIDX + k*81 + i*9) * HW
                          + (long)y*W_ + xb + lx0) * DD + z;
            #pragma unroll
            for (int xp = 0; xp < 4; xp++) {
                #pragma unroll
                for (int j = 0; j < 9; j++) {
                    float s0f, s1f; unpack2(mul2(acc[xp][j], scc), s0f, s1f);
                    out[obase + (long)j*HWD + (2*xp  )*DD] = s0f;
                    out[obase + (long)j*HWD + (2*xp+1)*DD] = s1f;
                }
            }
            const int yr = y + i - 4;
            const bool vrow = (yr >= 0) && (yr < H_);
            float m2w[16];
            #pragma unroll
            for (int n = 0; n < 16; n++) {
                int gxr = xb + lx0 - 4 + n;
                m2w[n] = (vrow && gxr >= 0 && gxr < W_)
                           ? __ldg(g_m2 + b*HW + yr*W_ + gxr) : 1.0f;
            }
            #pragma unroll
            for (int xi = 0; xi < PT; xi++) {
                #pragma unroll
                for (int j = 0; j < 9; j++) {
                    float mv = zedge ? m1x[xi] : (m1x[xi] * m2w[xi + j]);
                    omask[obase + (long)j*HWD + xi*DD] = mv;
                }
            }
        }
    }
}

// ---------------------------------------------------------------------------
__global__ void mask_sum_kernel(const float* __restrict__ a1,
                                const float* __restrict__ a2) {
    int n = blockIdx.x * blockDim.x + threadIdx.x;
    if (n >= B_*HW) return;
    const float4* p1 = (const float4*)(a1 + (size_t)n * DD);
    const float4* p2 = (const float4*)(a2 + (size_t)n * DD);
    float4 u = p1[0], v = p1[1];
    float s1 = u.x+u.y+u.z+u.w + v.x+v.y+v.z+v.w;
    u = p2[0]; v = p2[1];
    float s2 = u.x+u.y+u.z+u.w + v.x+v.y+v.z+v.w;
    g_m1[n] = fminf(fmaxf(s1, 0.f), 1.f);
    g_m2[n] = fminf(fmaxf(s2, 0.f), 1.f);
}

// ---------------------------------------------------------------------------
extern "C" void kernel_launch(void* const* d_in, const int* in_sizes, int n_in,
                              void* d_out, int out_size) {
    const float* f1 = (const float*)d_in[0];
    const float* a1 = (const float*)d_in[1];
    const float* f2 = (const float*)d_in[2];
    const float* a2 = (const float*)d_in[3];
    float* out      = (float*)d_out;
    float* out_mask = out + (long)B_ * NIDX * HWD;

    cudaFuncSetAttribute(cost_kernel,
                         cudaFuncAttributeMaxDynamicSharedMemorySize, SMEM_BYTES);

    mask_sum_kernel<<<(B_*HW + 255) / 256, 256>>>(a1, a2);

    cost_kernel<<<NTILE/4, 384, SMEM_BYTES>>>(f1, f2, out, out_mask);
}

// round 12
// speedup vs baseline: 1.4315x; 1.4315x over previous
#include <cuda_runtime.h>

typedef unsigned long long ull;

#define B_   4
#define C_   64
#define H_   96
#define W_   96
#define DD   8
#define HW   (H_*W_)          // 9216
#define HWD  (H_*W_*DD)       // 73728
#define NIDX 243

#define PX   32
#define PT   8
#define CCH  8
#define NST  72      // 9 i-shifts * 8 channel chunks
#define F1COL 36     // stride/4 odd -> perfect 4-phase LDS.128
#define F2COL 44
#define F1W  (CCH*8*F1COL)     // 2304 words
#define F2W  (CCH*10*F2COL)    // 3520 words
#define SMEM_WORDS (2*F1W + 2*F2W)
#define SMEM_BYTES (SMEM_WORDS*4)   // 46592 B -> 4 blocks/SM

__device__ float g_m1[B_*HW];
__device__ float g_m2[B_*HW];

__device__ __forceinline__ void fma2(ull &d, ull a, ull b) {
    asm("fma.rn.f32x2 %0, %1, %2, %0;" : "+l"(d) : "l"(a), "l"(b));
}
__device__ __forceinline__ ull mul2(ull a, ull b) {
    ull d; asm("mul.rn.f32x2 %0, %1, %2;" : "=l"(d) : "l"(a), "l"(b)); return d;
}
__device__ __forceinline__ ull pack2(float lo, float hi) {
    ull r; asm("mov.b64 %0, {%1, %2};" : "=l"(r) : "f"(lo), "f"(hi)); return r;
}
__device__ __forceinline__ void unpack2(ull v, float &lo, float &hi) {
    asm("mov.b64 {%0, %1}, %2;" : "=f"(lo), "=f"(hi) : "l"(v));
}

// ---------------------------------------------------------------------------
// 4 channels of correlation (R6 champion version: float4 LDS.128 + pack2).
// 6 LDS.128 (perfect 4-phase) feed 36 fma.f32x2 (72 MACs) per channel.
// ---------------------------------------------------------------------------
__device__ __forceinline__ void compute4(
    const float* __restrict__ f1s, const float* __restrict__ f2s,
    int clbase, int z, int zi, int lx0, ull acc[4][9])
{
    #pragma unroll
    for (int cu = 0; cu < 4; cu++) {
        const int cl = clbase + cu;
        const float4* p1 = (const float4*)(f1s + (cl*8 + z)*F1COL + lx0);
        float4 va = p1[0], vb = p1[1];
        ull vp[4];
        vp[0] = pack2(va.x, va.y); vp[1] = pack2(va.z, va.w);
        vp[2] = pack2(vb.x, vb.y); vp[3] = pack2(vb.z, vb.w);

        const float4* p2 = (const float4*)(f2s + (cl*10 + zi)*F2COL + lx0);
        float4 t0 = p2[0], t1 = p2[1], t2 = p2[2], t3 = p2[3];
        ull e[8], o[7];
        e[0] = pack2(t0.x, t0.y); e[1] = pack2(t0.z, t0.w);
        e[2] = pack2(t1.x, t1.y); e[3] = pack2(t1.z, t1.w);
        e[4] = pack2(t2.x, t2.y); e[5] = pack2(t2.z, t2.w);
        e[6] = pack2(t3.x, t3.y); e[7] = pack2(t3.z, t3.w);
        o[0] = pack2(t0.y, t0.z); o[1] = pack2(t0.w, t1.x);
        o[2] = pack2(t1.y, t1.z); o[3] = pack2(t1.w, t2.x);
        o[4] = pack2(t2.y, t2.z); o[5] = pack2(t2.w, t3.x);
        o[6] = pack2(t3.y, t3.z);

        #pragma unroll
        for (int xp = 0; xp < 4; xp++) {
            #pragma unroll
            for (int j = 0; j < 9; j++) {
                ull tp = (j & 1) ? o[xp + ((j-1)>>1)] : e[xp + (j>>1)];
                fma2(acc[xp][j], vp[xp], tp);
            }
        }
    }
}

// ---------------------------------------------------------------------------
// Cost + fused mask kernel, register-staged fill pipeline (R6 champion) +
// OOB i-group elision: when a group's f2 row is out of range, its compute
// stages and its buffer fills are skipped entirely (outputs are exact 0s via
// the cc==0 accumulator clear). Barrier pattern untouched.
// ---------------------------------------------------------------------------
__global__ void __launch_bounds__(96, 4)
cost_kernel(const float* __restrict__ f1g, const float* __restrict__ f2g,
            float* __restrict__ out, float* __restrict__ omask)
{
    extern __shared__ float sm[];
    float* f1b0 = sm;
    float* f1b1 = sm + F1W;
    float* f2b0 = sm + 2*F1W;
    float* f2b1 = sm + 2*F1W + F2W;

    const int tid = threadIdx.x;
    const int txg = tid & 3;
    const int z   = (tid >> 2) & 7;
    const int k   = tid >> 5;
    const int lx0 = txg * PT;
    const int xb  = blockIdx.x * PX;
    const int y   = blockIdx.y;
    const int b   = blockIdx.z;
    const int zi  = z + k;

    // ---- per-thread fill descriptors (hoisted index math)
    int  f2off[7], f2wb[7];
    bool f2ok[7];
    #pragma unroll
    for (int it = 0; it < 7; it++) {
        int idx = tid + it*96;
        int cl  = idx / 84;
        int r   = idx - cl*84;
        int col = r >> 1;
        int q   = r & 1;
        int gx  = xb - 4 + col;
        f2ok[it]  = (gx >= 0) && (gx < W_);
        f2off[it] = cl*HWD + gx*DD + q*4;
        f2wb[it]  = (cl*10 + 1 + q*4)*F2COL + col;
    }
    int  f1off[6], f1wb[6];
    bool f1ok[6];
    #pragma unroll
    for (int it = 0; it < 6; it++) {
        int idx = tid + it*96;
        f1ok[it] = idx < 512;
        int c = idx >> 6, r = idx & 63, col = r >> 1, q = r & 1;
        f1off[it] = c*HWD + col*DD + q*4;
        f1wb[it]  = (c*8 + q*4)*F1COL + col;
    }

    // zero the z-pad planes of both f2 buffers
    for (int n = tid; n < 2*CCH*2*F2COL; n += 96) {
        int p   = n / (CCH*2*F2COL);
        int r   = n - p*(CCH*2*F2COL);
        int cl  = r / (2*F2COL);
        int r2  = r - cl*(2*F2COL);
        int zp  = (r2 >= F2COL) ? 9 : 0;
        int col = (r2 >= F2COL) ? (r2 - F2COL) : r2;
        (p ? f2b1 : f2b0)[(cl*10 + zp)*F2COL + col] = 0.f;
    }

    float m1x[PT];
    {
        const float* m1p = g_m1 + b*HW + y*W_ + xb + lx0;
        float4 a = *(const float4*)(m1p);
        float4 c = *(const float4*)(m1p + 4);
        m1x[0]=a.x; m1x[1]=a.y; m1x[2]=a.z; m1x[3]=a.w;
        m1x[4]=c.x; m1x[5]=c.y; m1x[6]=c.z; m1x[7]=c.w;
    }
    const bool zedge = (zi == 0) || (zi == 9);

    // ---- prologue: fill stage 0 (i=0, cc=0). yr0 = y-4: valid when y>=4.
    {
        const int  yr0   = y - 4;
        const bool vrow0 = (yr0 >= 0);
        if (vrow0) {
            const float* s1 = f1g + ((size_t)(b*C_))*HWD + ((size_t)y*W_ + xb)*DD;
            #pragma unroll
            for (int it = 0; it < 6; it++) {
                if (f1ok[it]) {
                    float4 v = *(const float4*)(s1 + f1off[it]);
                    int wb = f1wb[it];
                    f1b0[wb]=v.x; f1b0[wb+F1COL]=v.y; f1b0[wb+2*F1COL]=v.z; f1b0[wb+3*F1COL]=v.w;
                }
            }
            const float* s2 = f2g + ((size_t)(b*C_))*HWD + (size_t)yr0 * (W_*DD);
            #pragma unroll
            for (int it = 0; it < 7; it++) {
                float4 v = make_float4(0.f,0.f,0.f,0.f);
                if (f2ok[it]) v = *(const float4*)(s2 + f2off[it]);
                int wb = f2wb[it];
                f2b0[wb]=v.x; f2b0[wb+F2COL]=v.y; f2b0[wb+2*F2COL]=v.z; f2b0[wb+3*F2COL]=v.w;
            }
        }
    }

    ull acc[4][9];

    for (int s = 0; s < NST; s++) {
        const int par = s & 1;
        __syncthreads();   // buf[par] filled; prior use of buf[par^1] done

        const float* f1s = par ? f1b1 : f1b0;
        const float* f2s = par ? f2b1 : f2b0;
        float* f1d = par ? f1b0 : f1b1;
        float* f2d = par ? f2b0 : f2b1;

        const int i  = s >> 3;
        const int cc = s & 7;
        const int yr_cur = y + i - 4;
        const bool vcur  = (yr_cur >= 0) && (yr_cur < H_);

        const int  sn    = s + 1;
        const bool hasn  = sn < NST;
        const int  in_   = sn >> 3;
        const int  ccn   = sn & 7;
        const int  yrn   = y + in_ - 4;
        const bool vrown = hasn && (yrn >= 0) && (yrn < H_);
        // if next group's row is OOB, nothing will read its buffers: skip fill

        // ---- phase 1: LDG f2-next into registers
        float4 Bv[7];
        if (vrown) {
            const float* s2 = f2g + ((size_t)(b*C_ + ccn*CCH))*HWD
                              + (size_t)yrn * (W_*DD);
            #pragma unroll
            for (int it = 0; it < 7; it++) {
                float4 v = make_float4(0.f,0.f,0.f,0.f);
                if (f2ok[it]) v = *(const float4*)(s2 + f2off[it]);
                Bv[it] = v;
            }
        }

        if (cc == 0) {
            #pragma unroll
            for (int xp = 0; xp < 4; xp++)
                #pragma unroll
                for (int j = 0; j < 9; j++) acc[xp][j] = 0ull;
        }

        // ---- phase 2: compute channels 0-3 (covers f2 LDG latency)
        if (vcur) compute4(f1s, f2s, 0, z, zi, lx0, acc);

        // ---- phase 3: STS f2-next
        if (vrown) {
            #pragma unroll
            for (int it = 0; it < 7; it++) {
                int wb = f2wb[it];
                f2d[wb]=Bv[it].x; f2d[wb+F2COL]=Bv[it].y;
                f2d[wb+2*F2COL]=Bv[it].z; f2d[wb+3*F2COL]=Bv[it].w;
            }
        }

        // ---- phase 4: LDG f1-next into registers
        float4 Av[6];
        if (vrown) {
            const float* s1 = f1g + ((size_t)(b*C_ + ccn*CCH))*HWD
                              + ((size_t)y*W_ + xb)*DD;
            #pragma unroll
            for (int it = 0; it < 6; it++) {
                float4 v = make_float4(0.f,0.f,0.f,0.f);
                if (f1ok[it]) v = *(const float4*)(s1 + f1off[it]);
                Av[it] = v;
            }
        }

        // ---- phase 5: compute channels 4-7 (covers f1 LDG latency)
        if (vcur) compute4(f1s, f2s, 4, z, zi, lx0, acc);

        // ---- phase 6: STS f1-next
        if (vrown) {
            #pragma unroll
            for (int it = 0; it < 6; it++) {
                if (f1ok[it]) {
                    int wb = f1wb[it];
                    f1d[wb]=Av[it].x; f1d[wb+F1COL]=Av[it].y;
                    f1d[wb+2*F1COL]=Av[it].z; f1d[wb+3*F1COL]=Av[it].w;
                }
            }
        }

        // ---- outputs at end of each i-group
        if (cc == 7) {
            const ull scc = pack2(1.0f/64.0f, 1.0f/64.0f);
            long obase = ((long)(b*NIDX + k*81 + i*9) * HW
                          + (long)y*W_ + xb + lx0) * DD + z;
            #pragma unroll
            for (int xp = 0; xp < 4; xp++) {
                #pragma unroll
                for (int j = 0; j < 9; j++) {
                    float s0f, s1f; unpack2(mul2(acc[xp][j], scc), s0f, s1f);
                    out[obase + (long)j*HWD + (2*xp  )*DD] = s0f;
                    out[obase + (long)j*HWD + (2*xp+1)*DD] = s1f;
                }
            }
            float m2w[16];
            #pragma unroll
            for (int n = 0; n < 16; n++) {
                int gxr = xb + lx0 - 4 + n;
                m2w[n] = (vcur && gxr >= 0 && gxr < W_)
                           ? __ldg(g_m2 + b*HW + yr_cur*W_ + gxr) : 1.0f;
            }
            #pragma unroll
            for (int xi = 0; xi < PT; xi++) {
                #pragma unroll
                for (int j = 0; j < 9; j++) {
                    float mv = zedge ? m1x[xi] : (m1x[xi] * m2w[xi + j]);
                    omask[obase + (long)j*HWD + xi*DD] = mv;
                }
            }
        }
    }
}

// ---------------------------------------------------------------------------
__global__ void mask_sum_kernel(const float* __restrict__ a1,
                                const float* __restrict__ a2) {
    int n = blockIdx.x * blockDim.x + threadIdx.x;
    if (n >= B_*HW) return;
    const float4* p1 = (const float4*)(a1 + (size_t)n * DD);
    const float4* p2 = (const float4*)(a2 + (size_t)n * DD);
    float4 u = p1[0], v = p1[1];
    float s1 = u.x+u.y+u.z+u.w + v.x+v.y+v.z+v.w;
    u = p2[0]; v = p2[1];
    float s2 = u.x+u.y+u.z+u.w + v.x+v.y+v.z+v.w;
    g_m1[n] = fminf(fmaxf(s1, 0.f), 1.f);
    g_m2[n] = fminf(fmaxf(s2, 0.f), 1.f);
}

// ---------------------------------------------------------------------------
extern "C" void kernel_launch(void* const* d_in, const int* in_sizes, int n_in,
                              void* d_out, int out_size) {
    const float* f1 = (const float*)d_in[0];
    const float* a1 = (const float*)d_in[1];
    const float* f2 = (const float*)d_in[2];
    const float* a2 = (const float*)d_in[3];
    float* out      = (float*)d_out;
    float* out_mask = out + (long)B_ * NIDX * HWD;

    mask_sum_kernel<<<(B_*HW + 255) / 256, 256>>>(a1, a2);

    dim3 g(W_ / PX, H_, B_);
    cost_kernel<<<g, 96, SMEM_BYTES>>>(f1, f2, out, out_mask);
}

// round 13
// speedup vs baseline: 1.7225x; 1.2034x over previous
#include <cuda_runtime.h>

typedef unsigned long long ull;

#define B_   4
#define C_   64
#define H_   96
#define W_   96
#define DD   8
#define HW   (H_*W_)          // 9216
#define HWD  (H_*W_*DD)       // 73728
#define NIDX 243

#define PX   32
#define PT   8
#define CCH  8
#define NST  72      // 9 i-shifts * 8 channel chunks
#define F1COL 36     // stride/4 odd -> perfect 4-phase LDS.128
#define F2COL 44
#define F1W  (CCH*8*F1COL)     // 2304 words
#define F2W  (CCH*10*F2COL)    // 3520 words
#define SMEM_WORDS (2*F1W + 2*F2W)
#define SMEM_BYTES (SMEM_WORDS*4)   // 46592 B -> 4 blocks/SM

__device__ float g_m1[B_*HW];
__device__ float g_m2[B_*HW];

__device__ __forceinline__ void fma2(ull &d, ull a, ull b) {
    asm("fma.rn.f32x2 %0, %1, %2, %0;" : "+l"(d) : "l"(a), "l"(b));
}
__device__ __forceinline__ ull mul2(ull a, ull b) {
    ull d; asm("mul.rn.f32x2 %0, %1, %2;" : "=l"(d) : "l"(a), "l"(b)); return d;
}
__device__ __forceinline__ ull pack2(float lo, float hi) {
    ull r; asm("mov.b64 %0, {%1, %2};" : "=l"(r) : "f"(lo), "f"(hi)); return r;
}
__device__ __forceinline__ void unpack2(ull v, float &lo, float &hi) {
    asm("mov.b64 {%0, %1}, %2;" : "=f"(lo), "=f"(hi) : "l"(v));
}
__device__ __forceinline__ void stcs(float* p, float v) {
    asm volatile("st.global.cs.f32 [%0], %1;" :: "l"(p), "f"(v));
}

// ---------------------------------------------------------------------------
// 4 channels of correlation (R6 champion form, byte-identical).
// 6 LDS.128 (perfect 4-phase) feed 36 fma.f32x2 (72 MACs) per channel.
// ---------------------------------------------------------------------------
__device__ __forceinline__ void compute4(
    const float* __restrict__ f1s, const float* __restrict__ f2s,
    int clbase, int z, int zi, int lx0, ull acc[4][9])
{
    #pragma unroll
    for (int cu = 0; cu < 4; cu++) {
        const int cl = clbase + cu;
        const float4* p1 = (const float4*)(f1s + (cl*8 + z)*F1COL + lx0);
        float4 va = p1[0], vb = p1[1];
        ull vp[4];
        vp[0] = pack2(va.x, va.y); vp[1] = pack2(va.z, va.w);
        vp[2] = pack2(vb.x, vb.y); vp[3] = pack2(vb.z, vb.w);

        const float4* p2 = (const float4*)(f2s + (cl*10 + zi)*F2COL + lx0);
        float4 t0 = p2[0], t1 = p2[1], t2 = p2[2], t3 = p2[3];
        ull e[8], o[7];
        e[0] = pack2(t0.x, t0.y); e[1] = pack2(t0.z, t0.w);
        e[2] = pack2(t1.x, t1.y); e[3] = pack2(t1.z, t1.w);
        e[4] = pack2(t2.x, t2.y); e[5] = pack2(t2.z, t2.w);
        e[6] = pack2(t3.x, t3.y); e[7] = pack2(t3.z, t3.w);
        o[0] = pack2(t0.y, t0.z); o[1] = pack2(t0.w, t1.x);
        o[2] = pack2(t1.y, t1.z); o[3] = pack2(t1.w, t2.x);
        o[4] = pack2(t2.y, t2.z); o[5] = pack2(t2.w, t3.x);
        o[6] = pack2(t3.y, t3.z);

        #pragma unroll
        for (int xp = 0; xp < 4; xp++) {
            #pragma unroll
            for (int j = 0; j < 9; j++) {
                ull tp = (j & 1) ? o[xp + ((j-1)>>1)] : e[xp + (j>>1)];
                fma2(acc[xp][j], vp[xp], tp);
            }
        }
    }
}

// ---------------------------------------------------------------------------
// Cost + fused mask kernel, register-staged fill pipeline (R6 champion).
// Changes vs R6: (a) output stores use st.global.cs (write-once data stops
// evicting the 9x-reused f2 rows from L2), (b) mask output moved from cc==7
// to cc==3 (splits the per-group 144-STG burst in half; mask depends only on
// (i,k,z,px), legal at any stage of group i). Pipeline/fills untouched.
// ---------------------------------------------------------------------------
__global__ void __launch_bounds__(96, 4)
cost_kernel(const float* __restrict__ f1g, const float* __restrict__ f2g,
            float* __restrict__ out, float* __restrict__ omask)
{
    extern __shared__ float sm[];
    float* f1b0 = sm;
    float* f1b1 = sm + F1W;
    float* f2b0 = sm + 2*F1W;
    float* f2b1 = sm + 2*F1W + F2W;

    const int tid = threadIdx.x;
    const int txg = tid & 3;
    const int z   = (tid >> 2) & 7;
    const int k   = tid >> 5;
    const int lx0 = txg * PT;
    const int xb  = blockIdx.x * PX;
    const int y   = blockIdx.y;
    const int b   = blockIdx.z;
    const int zi  = z + k;

    // ---- per-thread f2 fill descriptors (7 slots, idx = tid + 96*it)
    int  f2off[7], f2wb[7];
    bool f2ok[7];
    #pragma unroll
    for (int it = 0; it < 7; it++) {
        int idx = tid + it*96;
        int cl  = idx / 84;
        int r   = idx - cl*84;
        int col = r >> 1;
        int q   = r & 1;
        int gx  = xb - 4 + col;
        f2ok[it]  = (gx >= 0) && (gx < W_);
        f2off[it] = cl*HWD + gx*DD + q*4;
        f2wb[it]  = (cl*10 + 1 + q*4)*F2COL + col;
    }

    // zero the z-pad planes of both f2 buffers
    for (int n = tid; n < 2*CCH*2*F2COL; n += 96) {
        int p   = n / (CCH*2*F2COL);
        int r   = n - p*(CCH*2*F2COL);
        int cl  = r / (2*F2COL);
        int r2  = r - cl*(2*F2COL);
        int zp  = (r2 >= F2COL) ? 9 : 0;
        int col = (r2 >= F2COL) ? (r2 - F2COL) : r2;
        (p ? f2b1 : f2b0)[(cl*10 + zp)*F2COL + col] = 0.f;
    }

    float m1x[PT];
    {
        const float* m1p = g_m1 + b*HW + y*W_ + xb + lx0;
        float4 a = *(const float4*)(m1p);
        float4 c = *(const float4*)(m1p + 4);
        m1x[0]=a.x; m1x[1]=a.y; m1x[2]=a.z; m1x[3]=a.w;
        m1x[4]=c.x; m1x[5]=c.y; m1x[6]=c.z; m1x[7]=c.w;
    }
    const bool zedge = (zi == 0) || (zi == 9);

    // ---- prologue: fill stage 0 (i=0, cc=0). yr0 = y-4: valid when y>=4.
    {
        const float* s1 = f1g + ((size_t)(b*C_))*HWD + ((size_t)y*W_ + xb)*DD;
        #pragma unroll
        for (int it = 0; it < 6; it++) {
            int idx = tid + it*96;
            if (idx < 512) {
                int c = idx >> 6, r = idx & 63, col = r >> 1, q = r & 1;
                float4 v = *(const float4*)(s1 + (size_t)c*HWD + col*DD + q*4);
                int wb = (c*8 + q*4)*F1COL + col;
                f1b0[wb]=v.x; f1b0[wb+F1COL]=v.y; f1b0[wb+2*F1COL]=v.z; f1b0[wb+3*F1COL]=v.w;
            }
        }
        const int  yr0   = y - 4;
        const bool vrow0 = (yr0 >= 0);             // yr0 < H_ always (y < 96)
        const float* s2 = f2g + ((size_t)(b*C_))*HWD
                          + (size_t)(vrow0 ? yr0 : 0) * (W_*DD);
        #pragma unroll
        for (int it = 0; it < 7; it++) {
            float4 v = make_float4(0.f,0.f,0.f,0.f);
            if (vrow0 && f2ok[it]) v = *(const float4*)(s2 + f2off[it]);
            int wb = f2wb[it];
            f2b0[wb]=v.x; f2b0[wb+F2COL]=v.y; f2b0[wb+2*F2COL]=v.z; f2b0[wb+3*F2COL]=v.w;
        }
    }

    ull acc[4][9];

    for (int s = 0; s < NST; s++) {
        const int par = s & 1;
        __syncthreads();   // buf[par] filled; prior use of buf[par^1] done

        const float* f1s = par ? f1b1 : f1b0;
        const float* f2s = par ? f2b1 : f2b0;
        float* f1d = par ? f1b0 : f1b1;
        float* f2d = par ? f2b0 : f2b1;

        const int i  = s >> 3;
        const int cc = s & 7;

        // next-stage fill parameters
        const int  sn    = s + 1;
        const bool hasn  = sn < NST;
        const int  in_   = sn >> 3;
        const int  ccn   = sn & 7;
        const int  yrn   = y + in_ - 4;
        const bool vrown = hasn && (yrn >= 0) && (yrn < H_);

        // ---- phase 1: LDG f2-next into registers
        float4 Bv[7];
        {
            const float* s2 = f2g + ((size_t)(b*C_ + ccn*CCH))*HWD
                              + (size_t)(vrown ? yrn : 0) * (W_*DD);
            #pragma unroll
            for (int it = 0; it < 7; it++) {
                float4 v = make_float4(0.f,0.f,0.f,0.f);
                if (vrown && f2ok[it]) v = *(const float4*)(s2 + f2off[it]);
                Bv[it] = v;
            }
        }

        if (cc == 0) {
            #pragma unroll
            for (int xp = 0; xp < 4; xp++)
                #pragma unroll
                for (int j = 0; j < 9; j++) acc[xp][j] = 0ull;
        }

        // ---- phase 2: compute channels 0-3 (covers f2 LDG latency)
        compute4(f1s, f2s, 0, z, zi, lx0, acc);

        // ---- phase 3: STS f2-next
        if (hasn) {
            #pragma unroll
            for (int it = 0; it < 7; it++) {
                int wb = f2wb[it];
                f2d[wb]=Bv[it].x; f2d[wb+F2COL]=Bv[it].y;
                f2d[wb+2*F2COL]=Bv[it].z; f2d[wb+3*F2COL]=Bv[it].w;
            }
        }

        // ---- phase 4: LDG f1-next into registers
        float4 Av[6];
        {
            const float* s1 = f1g + ((size_t)(b*C_ + ccn*CCH))*HWD
                              + ((size_t)y*W_ + xb)*DD;
            #pragma unroll
            for (int it = 0; it < 6; it++) {
                int idx = tid + it*96;
                float4 v = make_float4(0.f,0.f,0.f,0.f);
                if (hasn && idx < 512) {
                    int c = idx >> 6, r = idx & 63, col = r >> 1, q = r & 1;
                    v = *(const float4*)(s1 + (size_t)c*HWD + col*DD + q*4);
                }
                Av[it] = v;
            }
        }

        // ---- phase 5: compute channels 4-7 (covers f1 LDG latency)
        compute4(f1s, f2s, 4, z, zi, lx0, acc);

        // ---- phase 6: STS f1-next
        if (hasn) {
            #pragma unroll
            for (int it = 0; it < 6; it++) {
                int idx = tid + it*96;
                if (idx < 512) {
                    int c = idx >> 6, r = idx & 63, col = r >> 1, q = r & 1;
                    int wb = (c*8 + q*4)*F1COL + col;
                    f1d[wb]=Av[it].x; f1d[wb+F1COL]=Av[it].y;
                    f1d[wb+2*F1COL]=Av[it].z; f1d[wb+3*F1COL]=Av[it].w;
                }
            }
        }

        // ---- mask output at cc==3 (independent of acc; spreads STG burst)
        if (cc == 3) {
            long obase = ((long)(b*NIDX + k*81 + i*9) * HW
                          + (long)y*W_ + xb + lx0) * DD + z;
            const int yr = y + i - 4;
            const bool vrow = (yr >= 0) && (yr < H_);
            float m2w[16];
            #pragma unroll
            for (int n = 0; n < 16; n++) {
                int gxr = xb + lx0 - 4 + n;
                m2w[n] = (vrow && gxr >= 0 && gxr < W_)
                           ? __ldg(g_m2 + b*HW + yr*W_ + gxr) : 1.0f;
            }
            #pragma unroll
            for (int xi = 0; xi < PT; xi++) {
                #pragma unroll
                for (int j = 0; j < 9; j++) {
                    float mv = zedge ? m1x[xi] : (m1x[xi] * m2w[xi + j]);
                    stcs(&omask[obase + (long)j*HWD + xi*DD], mv);
                }
            }
        }

        // ---- cost output at end of each i-group
        if (cc == 7) {
            const ull scc = pack2(1.0f/64.0f, 1.0f/64.0f);
            long obase = ((long)(b*NIDX + k*81 + i*9) * HW
                          + (long)y*W_ + xb + lx0) * DD + z;
            #pragma unroll
            for (int xp = 0; xp < 4; xp++) {
                #pragma unroll
                for (int j = 0; j < 9; j++) {
                    float s0f, s1f; unpack2(mul2(acc[xp][j], scc), s0f, s1f);
                    stcs(&out[obase + (long)j*HWD + (2*xp  )*DD], s0f);
                    stcs(&out[obase + (long)j*HWD + (2*xp+1)*DD], s1f);
                }
            }
        }
    }
}

// ---------------------------------------------------------------------------
__global__ void mask_sum_kernel(const float* __restrict__ a1,
                                const float* __restrict__ a2) {
    int n = blockIdx.x * blockDim.x + threadIdx.x;
    if (n >= B_*HW) return;
    const float4* p1 = (const float4*)(a1 + (size_t)n * DD);
    const float4* p2 = (const float4*)(a2 + (size_t)n * DD);
    float4 u = p1[0], v = p1[1];
    float s1 = u.x+u.y+u.z+u.w + v.x+v.y+v.z+v.w;
    u = p2[0]; v = p2[1];
    float s2 = u.x+u.y+u.z+u.w + v.x+v.y+v.z+v.w;
    g_m1[n] = fminf(fmaxf(s1, 0.f), 1.f);
    g_m2[n] = fminf(fmaxf(s2, 0.f), 1.f);
}

// ---------------------------------------------------------------------------
extern "C" void kernel_launch(void* const* d_in, const int* in_sizes, int n_in,
                              void* d_out, int out_size) {
    const float* f1 = (const float*)d_in[0];
    const float* a1 = (const float*)d_in[1];
    const float* f2 = (const float*)d_in[2];
    const float* a2 = (const float*)d_in[3];
    float* out      = (float*)d_out;
    float* out_mask = out + (long)B_ * NIDX * HWD;

    mask_sum_kernel<<<(B_*HW + 255) / 256, 256>>>(a1, a2);

    dim3 g(W_ / PX, H_, B_);
    cost_kernel<<<g, 96, SMEM_BYTES>>>(f1, f2, out, out_mask);
}

// round 14
// speedup vs baseline: 1.7369x; 1.0084x over previous
#include <cuda_runtime.h>

typedef unsigned long long ull;

#define B_   4
#define C_   64
#define H_   96
#define W_   96
#define DD   8
#define HW   (H_*W_)          // 9216
#define HWD  (H_*W_*DD)       // 73728
#define NIDX 243

#define PX   32
#define PT   8
#define CCH  8
#define NST  72      // 9 i-shifts * 8 channel chunks
#define F1COL 36     // stride/4 odd -> perfect 4-phase LDS.128
#define F2COL 44
#define F1W  (CCH*8*F1COL)     // 2304 words
#define F2W  (CCH*10*F2COL)    // 3520 words
#define SMEM_WORDS (2*F1W + 2*F2W)
#define SMEM_BYTES (SMEM_WORDS*4)   // 46592 B -> 4 blocks/SM

#define OB_STRIDE (9L*HW*DD)   // 663552: output offset per i-group

__device__ float g_m1[B_*HW];
__device__ float g_m2[B_*HW];

__device__ __forceinline__ void fma2(ull &d, ull a, ull b) {
    asm("fma.rn.f32x2 %0, %1, %2, %0;" : "+l"(d) : "l"(a), "l"(b));
}
__device__ __forceinline__ ull mul2(ull a, ull b) {
    ull d; asm("mul.rn.f32x2 %0, %1, %2;" : "=l"(d) : "l"(a), "l"(b)); return d;
}
__device__ __forceinline__ ull pack2(float lo, float hi) {
    ull r; asm("mov.b64 %0, {%1, %2};" : "=l"(r) : "f"(lo), "f"(hi)); return r;
}
__device__ __forceinline__ void unpack2(ull v, float &lo, float &hi) {
    asm("mov.b64 {%0, %1}, %2;" : "=f"(lo), "=f"(hi) : "l"(v));
}
__device__ __forceinline__ void stcs(float* p, float v) {
    asm volatile("st.global.cs.f32 [%0], %1;" :: "l"(p), "f"(v));
}

// ---------------------------------------------------------------------------
// 4 channels of correlation (R6 champion form, byte-identical).
// 6 LDS.128 (perfect 4-phase) feed 36 fma.f32x2 (72 MACs) per channel.
// ---------------------------------------------------------------------------
__device__ __forceinline__ void compute4(
    const float* __restrict__ f1s, const float* __restrict__ f2s,
    int clbase, int z, int zi, int lx0, ull acc[4][9])
{
    #pragma unroll
    for (int cu = 0; cu < 4; cu++) {
        const int cl = clbase + cu;
        const float4* p1 = (const float4*)(f1s + (cl*8 + z)*F1COL + lx0);
        float4 va = p1[0], vb = p1[1];
        ull vp[4];
        vp[0] = pack2(va.x, va.y); vp[1] = pack2(va.z, va.w);
        vp[2] = pack2(vb.x, vb.y); vp[3] = pack2(vb.z, vb.w);

        const float4* p2 = (const float4*)(f2s + (cl*10 + zi)*F2COL + lx0);
        float4 t0 = p2[0], t1 = p2[1], t2 = p2[2], t3 = p2[3];
        ull e[8], o[7];
        e[0] = pack2(t0.x, t0.y); e[1] = pack2(t0.z, t0.w);
        e[2] = pack2(t1.x, t1.y); e[3] = pack2(t1.z, t1.w);
        e[4] = pack2(t2.x, t2.y); e[5] = pack2(t2.z, t2.w);
        e[6] = pack2(t3.x, t3.y); e[7] = pack2(t3.z, t3.w);
        o[0] = pack2(t0.y, t0.z); o[1] = pack2(t0.w, t1.x);
        o[2] = pack2(t1.y, t1.z); o[3] = pack2(t1.w, t2.x);
        o[4] = pack2(t2.y, t2.z); o[5] = pack2(t2.w, t3.x);
        o[6] = pack2(t3.y, t3.z);

        #pragma unroll
        for (int xp = 0; xp < 4; xp++) {
            #pragma unroll
            for (int j = 0; j < 9; j++) {
                ull tp = (j & 1) ? o[xp + ((j-1)>>1)] : e[xp + (j>>1)];
                fma2(acc[xp][j], vp[xp], tp);
            }
        }
    }
}

// ---------------------------------------------------------------------------
// Cost + fused mask kernel, register-staged fill pipeline (R13 champion).
// Changes vs R13 (ALU diet only; phases/guards/barriers untouched):
//  (a) f1 fill index math hoisted into per-thread descriptors (like f2's),
//  (b) output base offset computed incrementally (ob0 + i*OB_STRIDE).
// ---------------------------------------------------------------------------
__global__ void __launch_bounds__(96, 4)
cost_kernel(const float* __restrict__ f1g, const float* __restrict__ f2g,
            float* __restrict__ out, float* __restrict__ omask)
{
    extern __shared__ float sm[];
    float* f1b0 = sm;
    float* f1b1 = sm + F1W;
    float* f2b0 = sm + 2*F1W;
    float* f2b1 = sm + 2*F1W + F2W;

    const int tid = threadIdx.x;
    const int txg = tid & 3;
    const int z   = (tid >> 2) & 7;
    const int k   = tid >> 5;
    const int lx0 = txg * PT;
    const int xb  = blockIdx.x * PX;
    const int y   = blockIdx.y;
    const int b   = blockIdx.z;
    const int zi  = z + k;

    // ---- per-thread f2 fill descriptors (7 slots, idx = tid + 96*it)
    int  f2off[7], f2wb[7];
    bool f2ok[7];
    #pragma unroll
    for (int it = 0; it < 7; it++) {
        int idx = tid + it*96;
        int cl  = idx / 84;
        int r   = idx - cl*84;
        int col = r >> 1;
        int q   = r & 1;
        int gx  = xb - 4 + col;
        f2ok[it]  = (gx >= 0) && (gx < W_);
        f2off[it] = cl*HWD + gx*DD + q*4;
        f2wb[it]  = (cl*10 + 1 + q*4)*F2COL + col;
    }
    // ---- per-thread f1 fill descriptors (6 slots, idx = tid + 96*it)
    int  f1off[6], f1wb[6];
    bool f1ok[6];
    #pragma unroll
    for (int it = 0; it < 6; it++) {
        int idx = tid + it*96;
        f1ok[it] = idx < 512;
        int c = idx >> 6, r = idx & 63, col = r >> 1, q = r & 1;
        f1off[it] = c*HWD + col*DD + q*4;
        f1wb[it]  = (c*8 + q*4)*F1COL + col;
    }

    // zero the z-pad planes of both f2 buffers
    for (int n = tid; n < 2*CCH*2*F2COL; n += 96) {
        int p   = n / (CCH*2*F2COL);
        int r   = n - p*(CCH*2*F2COL);
        int cl  = r / (2*F2COL);
        int r2  = r - cl*(2*F2COL);
        int zp  = (r2 >= F2COL) ? 9 : 0;
        int col = (r2 >= F2COL) ? (r2 - F2COL) : r2;
        (p ? f2b1 : f2b0)[(cl*10 + zp)*F2COL + col] = 0.f;
    }

    float m1x[PT];
    {
        const float* m1p = g_m1 + b*HW + y*W_ + xb + lx0;
        float4 a = *(const float4*)(m1p);
        float4 c = *(const float4*)(m1p + 4);
        m1x[0]=a.x; m1x[1]=a.y; m1x[2]=a.z; m1x[3]=a.w;
        m1x[4]=c.x; m1x[5]=c.y; m1x[6]=c.z; m1x[7]=c.w;
    }
    const bool zedge = (zi == 0) || (zi == 9);

    // output base for i=0 (one-time chain; branches add i*OB_STRIDE)
    const long ob0 = ((long)(b*NIDX + k*81) * HW
                      + (long)y*W_ + xb + lx0) * DD + z;

    // ---- prologue: fill stage 0 (i=0, cc=0). yr0 = y-4: valid when y>=4.
    {
        const float* s1 = f1g + ((size_t)(b*C_))*HWD + ((size_t)y*W_ + xb)*DD;
        #pragma unroll
        for (int it = 0; it < 6; it++) {
            if (f1ok[it]) {
                float4 v = *(const float4*)(s1 + f1off[it]);
                int wb = f1wb[it];
                f1b0[wb]=v.x; f1b0[wb+F1COL]=v.y; f1b0[wb+2*F1COL]=v.z; f1b0[wb+3*F1COL]=v.w;
            }
        }
        const int  yr0   = y - 4;
        const bool vrow0 = (yr0 >= 0);             // yr0 < H_ always (y < 96)
        const float* s2 = f2g + ((size_t)(b*C_))*HWD
                          + (size_t)(vrow0 ? yr0 : 0) * (W_*DD);
        #pragma unroll
        for (int it = 0; it < 7; it++) {
            float4 v = make_float4(0.f,0.f,0.f,0.f);
            if (vrow0 && f2ok[it]) v = *(const float4*)(s2 + f2off[it]);
            int wb = f2wb[it];
            f2b0[wb]=v.x; f2b0[wb+F2COL]=v.y; f2b0[wb+2*F2COL]=v.z; f2b0[wb+3*F2COL]=v.w;
        }
    }

    ull acc[4][9];

    for (int s = 0; s < NST; s++) {
        const int par = s & 1;
        __syncthreads();   // buf[par] filled; prior use of buf[par^1] done

        const float* f1s = par ? f1b1 : f1b0;
        const float* f2s = par ? f2b1 : f2b0;
        float* f1d = par ? f1b0 : f1b1;
        float* f2d = par ? f2b0 : f2b1;

        const int i  = s >> 3;
        const int cc = s & 7;

        // next-stage fill parameters
        const int  sn    = s + 1;
        const bool hasn  = sn < NST;
        const int  in_   = sn >> 3;
        const int  ccn   = sn & 7;
        const int  yrn   = y + in_ - 4;
        const bool vrown = hasn && (yrn >= 0) && (yrn < H_);

        // ---- phase 1: LDG f2-next into registers
        float4 Bv[7];
        {
            const float* s2 = f2g + ((size_t)(b*C_ + ccn*CCH))*HWD
                              + (size_t)(vrown ? yrn : 0) * (W_*DD);
            #pragma unroll
            for (int it = 0; it < 7; it++) {
                float4 v = make_float4(0.f,0.f,0.f,0.f);
                if (vrown && f2ok[it]) v = *(const float4*)(s2 + f2off[it]);
                Bv[it] = v;
            }
        }

        if (cc == 0) {
            #pragma unroll
            for (int xp = 0; xp < 4; xp++)
                #pragma unroll
                for (int j = 0; j < 9; j++) acc[xp][j] = 0ull;
        }

        // ---- phase 2: compute channels 0-3 (covers f2 LDG latency)
        compute4(f1s, f2s, 0, z, zi, lx0, acc);

        // ---- phase 3: STS f2-next
        if (hasn) {
            #pragma unroll
            for (int it = 0; it < 7; it++) {
                int wb = f2wb[it];
                f2d[wb]=Bv[it].x; f2d[wb+F2COL]=Bv[it].y;
                f2d[wb+2*F2COL]=Bv[it].z; f2d[wb+3*F2COL]=Bv[it].w;
            }
        }

        // ---- phase 4: LDG f1-next into registers
        float4 Av[6];
        {
            const float* s1 = f1g + ((size_t)(b*C_ + ccn*CCH))*HWD
                              + ((size_t)y*W_ + xb)*DD;
            #pragma unroll
            for (int it = 0; it < 6; it++) {
                float4 v = make_float4(0.f,0.f,0.f,0.f);
                if (hasn && f1ok[it]) v = *(const float4*)(s1 + f1off[it]);
                Av[it] = v;
            }
        }

        // ---- phase 5: compute channels 4-7 (covers f1 LDG latency)
        compute4(f1s, f2s, 4, z, zi, lx0, acc);

        // ---- phase 6: STS f1-next
        if (hasn) {
            #pragma unroll
            for (int it = 0; it < 6; it++) {
                if (f1ok[it]) {
                    int wb = f1wb[it];
                    f1d[wb]=Av[it].x; f1d[wb+F1COL]=Av[it].y;
                    f1d[wb+2*F1COL]=Av[it].z; f1d[wb+3*F1COL]=Av[it].w;
                }
            }
        }

        // ---- mask output at cc==3 (independent of acc; spreads STG burst)
        if (cc == 3) {
            long obase = ob0 + (long)i * OB_STRIDE;
            const int yr = y + i - 4;
            const bool vrow = (yr >= 0) && (yr < H_);
            float m2w[16];
            #pragma unroll
            for (int n = 0; n < 16; n++) {
                int gxr = xb + lx0 - 4 + n;
                m2w[n] = (vrow && gxr >= 0 && gxr < W_)
                           ? __ldg(g_m2 + b*HW + yr*W_ + gxr) : 1.0f;
            }
            #pragma unroll
            for (int xi = 0; xi < PT; xi++) {
                #pragma unroll
                for (int j = 0; j < 9; j++) {
                    float mv = zedge ? m1x[xi] : (m1x[xi] * m2w[xi + j]);
                    stcs(&omask[obase + (long)j*HWD + xi*DD], mv);
                }
            }
        }

        // ---- cost output at end of each i-group
        if (cc == 7) {
            const ull scc = pack2(1.0f/64.0f, 1.0f/64.0f);
            long obase = ob0 + (long)i * OB_STRIDE;
            #pragma unroll
            for (int xp = 0; xp < 4; xp++) {
                #pragma unroll
                for (int j = 0; j < 9; j++) {
                    float s0f, s1f; unpack2(mul2(acc[xp][j], scc), s0f, s1f);
                    stcs(&out[obase + (long)j*HWD + (2*xp  )*DD], s0f);
                    stcs(&out[obase + (long)j*HWD + (2*xp+1)*DD], s1f);
                }
            }
        }
    }
}

// ---------------------------------------------------------------------------
__global__ void mask_sum_kernel(const float* __restrict__ a1,
                                const float* __restrict__ a2) {
    int n = blockIdx.x * blockDim.x + threadIdx.x;
    if (n >= B_*HW) return;
    const float4* p1 = (const float4*)(a1 + (size_t)n * DD);
    const float4* p2 = (const float4*)(a2 + (size_t)n * DD);
    float4 u = p1[0], v = p1[1];
    float s1 = u.x+u.y+u.z+u.w + v.x+v.y+v.z+v.w;
    u = p2[0]; v = p2[1];
    float s2 = u.x+u.y+u.z+u.w + v.x+v.y+v.z+v.w;
    g_m1[n] = fminf(fmaxf(s1, 0.f), 1.f);
    g_m2[n] = fminf(fmaxf(s2, 0.f), 1.f);
}

// ---------------------------------------------------------------------------
extern "C" void kernel_launch(void* const* d_in, const int* in_sizes, int n_in,
                              void* d_out, int out_size) {
    const float* f1 = (const float*)d_in[0];
    const float* a1 = (const float*)d_in[1];
    const float* f2 = (const float*)d_in[2];
    const float* a2 = (const float*)d_in[3];
    float* out      = (float*)d_out;
    float* out_mask = out + (long)B_ * NIDX * HWD;

    mask_sum_kernel<<<(B_*HW + 255) / 256, 256>>>(a1, a2);

    dim3 g(W_ / PX, H_, B_);
    cost_kernel<<<g, 96, SMEM_BYTES>>>(f1, f2, out, out_mask);
}